// round 1
// baseline (speedup 1.0000x reference)
#include <cuda_runtime.h>

#define BATCH 512
#define T     25
#define H     100
#define G     400      // 4*H, gate width
#define FCW   128
#define NC    2
#define BROWS 4
#define NBLK  (BATCH / BROWS)   // 128 blocks
#define NTHR  512

// Scratch for precomputed zx[b][t][G] = emb[feat[b,t]] @ k1[0:H,:] + b1
__device__ float g_zx[(size_t)BATCH * T * G];   // 20.48 MB

__device__ __forceinline__ float sigm(float x) {
    return 1.0f / (1.0f + __expf(-x));
}
__device__ __forceinline__ float mytanh(float x) {
    float e = __expf(-2.0f * x);
    return (1.0f - e) / (1.0f + e);
}

// ---------------------------------------------------------------------------
// Kernel A: embedding gather + input-projection GEMM for layer 1 (parallel
// over all (b,t)). One block per batch row; 25 timesteps share weight loads.
// ---------------------------------------------------------------------------
__global__ void __launch_bounds__(NTHR, 1) embed_zx_kernel(
    const int*   __restrict__ feats,     // [BATCH, T]
    const float* __restrict__ emb,       // [VOCAB, H]
    const float* __restrict__ k1,        // [2H, G]
    const float* __restrict__ b1,        // [G]
    float*       __restrict__ zx)        // [BATCH, T, G]
{
    __shared__ __align__(16) float xs[T * H];   // [t][k], 2500 floats
    const int b   = blockIdx.x;
    const int tid = threadIdx.x;

    for (int i = tid; i < T * H; i += NTHR) {
        int t = i / H, k = i % H;
        long long f = feats[b * T + t];
        xs[i] = emb[f * H + k];
    }
    __syncthreads();

    if (tid < G) {
        const int c = tid;
        float acc[T];
        const float bias = b1[c];
        #pragma unroll
        for (int t = 0; t < T; t++) acc[t] = bias;

        const float4* xsv = (const float4*)xs;  // [t][H/4]
        #pragma unroll 5
        for (int kk = 0; kk < H / 4; kk++) {
            float w0 = k1[(kk * 4 + 0) * G + c];
            float w1 = k1[(kk * 4 + 1) * G + c];
            float w2 = k1[(kk * 4 + 2) * G + c];
            float w3 = k1[(kk * 4 + 3) * G + c];
            #pragma unroll
            for (int t = 0; t < T; t++) {
                float4 xv = xsv[t * (H / 4) + kk];
                acc[t] += xv.x * w0 + xv.y * w1 + xv.z * w2 + xv.w * w3;
            }
        }
        #pragma unroll
        for (int t = 0; t < T; t++)
            zx[((long long)b * T + t) * G + c] = acc[t];
    }
}

// ---------------------------------------------------------------------------
// Kernel B: persistent per-batch-slice LSTM recurrence + FC head.
// 128 blocks x 4 rows. k1_h (160KB) cached in smem; k2 streamed from L2.
// ---------------------------------------------------------------------------
#define SM_K1H   0
#define SM_H1    (H * G)                  // 40000
#define SM_H2    (SM_H1 + BROWS * H)      // 40400
#define SM_Z     (SM_H2 + BROWS * H)      // 40800
#define SM_B2    (SM_Z + BROWS * G)       // 42400
#define SM_FLOATS (SM_B2 + G)             // 42800 floats = 171200 B

__global__ void __launch_bounds__(NTHR, 1) lstm_seq_kernel(
    const float* __restrict__ zx,        // [BATCH, T, G]
    const float* __restrict__ k1,        // [2H, G]
    const float* __restrict__ k2,        // [2H, G]
    const float* __restrict__ b2,        // [G]
    const float* __restrict__ wfc1,      // [H, FCW]
    const float* __restrict__ bfc1,      // [FCW]
    const float* __restrict__ wfc2,      // [FCW, NC]
    const float* __restrict__ bfc2,      // [NC]
    float*       __restrict__ out)       // [BATCH, NC]
{
    extern __shared__ __align__(16) float sm[];
    float* k1h = sm + SM_K1H;    // [H][G]  (h-recurrence half of k1)
    float* h1  = sm + SM_H1;     // [BROWS][H]
    float* h2  = sm + SM_H2;     // [BROWS][H]
    float* zs  = sm + SM_Z;      // [BROWS][G]
    float* b2s = sm + SM_B2;     // [G]

    const int tid = threadIdx.x;
    const int b0  = blockIdx.x * BROWS;

    for (int i = tid; i < H * G; i += NTHR) k1h[i] = k1[H * G + i];
    for (int i = tid; i < BROWS * H; i += NTHR) { h1[i] = 0.0f; h2[i] = 0.0f; }
    for (int i = tid; i < G; i += NTHR) b2s[i] = b2[i];
    __syncthreads();

    float c1 = 0.0f, c2 = 0.0f;          // cell state owned by thread (tid<400)
    const int ur = tid / H;              // update row
    const int uu = tid % H;              // update unit

    for (int t = 0; t < T; t++) {
        // ---- layer 1: z = zx[t] + h1_prev @ k1h ----
        if (tid < G) {
            const int c = tid;
            const float* zxp = zx + ((long long)b0 * T + t) * G + c;
            float a0 = zxp[0 * T * G];
            float a1 = zxp[1 * T * G];
            float a2 = zxp[2 * T * G];
            float a3 = zxp[3 * T * G];
            const float4* hv = (const float4*)h1;
            #pragma unroll 5
            for (int kk = 0; kk < H / 4; kk++) {
                float4 v0 = hv[0 * (H / 4) + kk];
                float4 v1 = hv[1 * (H / 4) + kk];
                float4 v2 = hv[2 * (H / 4) + kk];
                float4 v3 = hv[3 * (H / 4) + kk];
                float w0 = k1h[(kk * 4 + 0) * G + c];
                float w1 = k1h[(kk * 4 + 1) * G + c];
                float w2 = k1h[(kk * 4 + 2) * G + c];
                float w3 = k1h[(kk * 4 + 3) * G + c];
                a0 += v0.x * w0 + v0.y * w1 + v0.z * w2 + v0.w * w3;
                a1 += v1.x * w0 + v1.y * w1 + v1.z * w2 + v1.w * w3;
                a2 += v2.x * w0 + v2.y * w1 + v2.z * w2 + v2.w * w3;
                a3 += v3.x * w0 + v3.y * w1 + v3.z * w2 + v3.w * w3;
            }
            zs[0 * G + c] = a0;
            zs[1 * G + c] = a1;
            zs[2 * G + c] = a2;
            zs[3 * G + c] = a3;
        }
        __syncthreads();

        // ---- layer 1 gates ----
        if (tid < BROWS * H) {
            float zi = zs[ur * G + uu];
            float zj = zs[ur * G + uu + H];
            float zf = zs[ur * G + uu + 2 * H];
            float zo = zs[ur * G + uu + 3 * H];
            c1 = c1 * sigm(zf + 1.0f) + sigm(zi) * mytanh(zj);
            h1[ur * H + uu] = mytanh(c1) * sigm(zo);
        }
        __syncthreads();

        // ---- layer 2: z = [h1_new, h2_prev] @ k2 + b2 ----
        if (tid < G) {
            const int c = tid;
            float a0 = b2s[c], a1 = a0, a2 = a0, a3 = a0;
            const float4* h1v = (const float4*)h1;
            const float4* h2v = (const float4*)h2;
            #pragma unroll 5
            for (int kk = 0; kk < H / 4; kk++) {
                float4 v0 = h1v[0 * (H / 4) + kk];
                float4 v1 = h1v[1 * (H / 4) + kk];
                float4 v2 = h1v[2 * (H / 4) + kk];
                float4 v3 = h1v[3 * (H / 4) + kk];
                float w0 = __ldg(&k2[(kk * 4 + 0) * G + c]);
                float w1 = __ldg(&k2[(kk * 4 + 1) * G + c]);
                float w2 = __ldg(&k2[(kk * 4 + 2) * G + c]);
                float w3 = __ldg(&k2[(kk * 4 + 3) * G + c]);
                a0 += v0.x * w0 + v0.y * w1 + v0.z * w2 + v0.w * w3;
                a1 += v1.x * w0 + v1.y * w1 + v1.z * w2 + v1.w * w3;
                a2 += v2.x * w0 + v2.y * w1 + v2.z * w2 + v2.w * w3;
                a3 += v3.x * w0 + v3.y * w1 + v3.z * w2 + v3.w * w3;
            }
            #pragma unroll 5
            for (int kk = 0; kk < H / 4; kk++) {
                float4 v0 = h2v[0 * (H / 4) + kk];
                float4 v1 = h2v[1 * (H / 4) + kk];
                float4 v2 = h2v[2 * (H / 4) + kk];
                float4 v3 = h2v[3 * (H / 4) + kk];
                float w0 = __ldg(&k2[(H + kk * 4 + 0) * G + c]);
                float w1 = __ldg(&k2[(H + kk * 4 + 1) * G + c]);
                float w2 = __ldg(&k2[(H + kk * 4 + 2) * G + c]);
                float w3 = __ldg(&k2[(H + kk * 4 + 3) * G + c]);
                a0 += v0.x * w0 + v0.y * w1 + v0.z * w2 + v0.w * w3;
                a1 += v1.x * w0 + v1.y * w1 + v1.z * w2 + v1.w * w3;
                a2 += v2.x * w0 + v2.y * w1 + v2.z * w2 + v2.w * w3;
                a3 += v3.x * w0 + v3.y * w1 + v3.z * w2 + v3.w * w3;
            }
            zs[0 * G + c] = a0;
            zs[1 * G + c] = a1;
            zs[2 * G + c] = a2;
            zs[3 * G + c] = a3;
        }
        __syncthreads();

        // ---- layer 2 gates ----
        if (tid < BROWS * H) {
            float zi = zs[ur * G + uu];
            float zj = zs[ur * G + uu + H];
            float zf = zs[ur * G + uu + 2 * H];
            float zo = zs[ur * G + uu + 3 * H];
            c2 = c2 * sigm(zf + 1.0f) + sigm(zi) * mytanh(zj);
            h2[ur * H + uu] = mytanh(c2) * sigm(zo);
        }
        __syncthreads();
    }

    // ---- FC head: fc1 = h2 @ wfc1 + bfc1 ; pred = fc1 @ wfc2 + bfc2 ----
    if (tid < BROWS * FCW) {
        int r = tid / FCW, j = tid % FCW;
        float a = bfc1[j];
        #pragma unroll 4
        for (int k = 0; k < H; k++)
            a += h2[r * H + k] * wfc1[k * FCW + j];
        zs[r * FCW + j] = a;   // reuse zs as fc1 buffer
    }
    __syncthreads();
    if (tid < BROWS * NC) {
        int r = tid / NC, cc = tid % NC;
        float a = bfc2[cc];
        #pragma unroll 8
        for (int k = 0; k < FCW; k++)
            a += zs[r * FCW + k] * wfc2[k * NC + cc];
        out[(b0 + r) * NC + cc] = a;
    }
}

// ---------------------------------------------------------------------------
extern "C" void kernel_launch(void* const* d_in, const int* in_sizes, int n_in,
                              void* d_out, int out_size)
{
    const int*   feats = (const int*)  d_in[0];  // [512,25] int32
    const float* emb   = (const float*)d_in[1];  // [400001,100]
    const float* k1    = (const float*)d_in[2];  // [200,400]
    const float* b1    = (const float*)d_in[3];  // [400]
    const float* k2    = (const float*)d_in[4];  // [200,400]
    const float* b2    = (const float*)d_in[5];  // [400]
    const float* wfc1  = (const float*)d_in[6];  // [100,128]
    const float* bfc1  = (const float*)d_in[7];  // [128]
    const float* wfc2  = (const float*)d_in[8];  // [128,2]
    const float* bfc2  = (const float*)d_in[9];  // [2]
    float* out = (float*)d_out;                  // [512,2]

    float* zx = nullptr;
    cudaGetSymbolAddress((void**)&zx, g_zx);

    cudaFuncSetAttribute(lstm_seq_kernel,
                         cudaFuncAttributeMaxDynamicSharedMemorySize,
                         SM_FLOATS * (int)sizeof(float));

    embed_zx_kernel<<<BATCH, NTHR>>>(feats, emb, k1, b1, zx);
    lstm_seq_kernel<<<NBLK, NTHR, SM_FLOATS * sizeof(float)>>>(
        zx, k1, k2, b2, wfc1, bfc1, wfc2, bfc2, out);
}

// round 2
// speedup vs baseline: 1.0013x; 1.0013x over previous
#include <cuda_runtime.h>

#define BATCH 512
#define T     25
#define H     100
#define G     400      // 4*H, gate width
#define FCW   128
#define NC    2
#define BROWS 4
#define NBLK  (BATCH / BROWS)   // 128 blocks
#define NTHR  512

// Scratch for precomputed zx[b][t][G] = emb[feat[b,t]] @ k1[0:H,:] + b1
__device__ float g_zx[(size_t)BATCH * T * G];   // 20.48 MB

__device__ __forceinline__ float sigm(float x) {
    return 1.0f / (1.0f + __expf(-x));
}
__device__ __forceinline__ float mytanh(float x) {
    float e = __expf(-2.0f * x);
    return (1.0f - e) / (1.0f + e);
}

// ---------------------------------------------------------------------------
// Kernel A: embedding gather + input-projection GEMM for layer 1 (parallel
// over all (b,t)). One block per batch row; 25 timesteps share weight loads.
// ---------------------------------------------------------------------------
__global__ void __launch_bounds__(NTHR, 1) embed_zx_kernel(
    const int*   __restrict__ feats,     // [BATCH, T]
    const float* __restrict__ emb,       // [VOCAB, H]
    const float* __restrict__ k1,        // [2H, G]
    const float* __restrict__ b1,        // [G]
    float*       __restrict__ zx)        // [BATCH, T, G]
{
    __shared__ __align__(16) float xs[T * H];   // [t][k], 2500 floats
    const int b   = blockIdx.x;
    const int tid = threadIdx.x;

    for (int i = tid; i < T * H; i += NTHR) {
        int t = i / H, k = i % H;
        long long f = feats[b * T + t];
        xs[i] = emb[f * H + k];
    }
    __syncthreads();

    if (tid < G) {
        const int c = tid;
        float acc[T];
        const float bias = b1[c];
        #pragma unroll
        for (int t = 0; t < T; t++) acc[t] = bias;

        const float4* xsv = (const float4*)xs;  // [t][H/4]
        #pragma unroll 5
        for (int kk = 0; kk < H / 4; kk++) {
            float w0 = k1[(kk * 4 + 0) * G + c];
            float w1 = k1[(kk * 4 + 1) * G + c];
            float w2 = k1[(kk * 4 + 2) * G + c];
            float w3 = k1[(kk * 4 + 3) * G + c];
            #pragma unroll
            for (int t = 0; t < T; t++) {
                float4 xv = xsv[t * (H / 4) + kk];
                acc[t] += xv.x * w0 + xv.y * w1 + xv.z * w2 + xv.w * w3;
            }
        }
        #pragma unroll
        for (int t = 0; t < T; t++)
            zx[((long long)b * T + t) * G + c] = acc[t];
    }
}

// ---------------------------------------------------------------------------
// Kernel B: persistent per-batch-slice LSTM recurrence + FC head.
// 128 blocks x 4 rows. k1_h (160KB) cached in smem; k2 streamed from L2.
// ---------------------------------------------------------------------------
#define SM_K1H   0
#define SM_H1    (H * G)                  // 40000
#define SM_H2    (SM_H1 + BROWS * H)      // 40400
#define SM_Z     (SM_H2 + BROWS * H)      // 40800
#define SM_B2    (SM_Z + BROWS * G)       // 42400
#define SM_FLOATS (SM_B2 + G)             // 42800 floats = 171200 B

__global__ void __launch_bounds__(NTHR, 1) lstm_seq_kernel(
    const float* __restrict__ zx,        // [BATCH, T, G]
    const float* __restrict__ k1,        // [2H, G]
    const float* __restrict__ k2,        // [2H, G]
    const float* __restrict__ b2,        // [G]
    const float* __restrict__ wfc1,      // [H, FCW]
    const float* __restrict__ bfc1,      // [FCW]
    const float* __restrict__ wfc2,      // [FCW, NC]
    const float* __restrict__ bfc2,      // [NC]
    float*       __restrict__ out)       // [BATCH, NC]
{
    extern __shared__ __align__(16) float sm[];
    float* k1h = sm + SM_K1H;    // [H][G]  (h-recurrence half of k1)
    float* h1  = sm + SM_H1;     // [BROWS][H]
    float* h2  = sm + SM_H2;     // [BROWS][H]
    float* zs  = sm + SM_Z;      // [BROWS][G]
    float* b2s = sm + SM_B2;     // [G]

    const int tid = threadIdx.x;
    const int b0  = blockIdx.x * BROWS;

    for (int i = tid; i < H * G; i += NTHR) k1h[i] = k1[H * G + i];
    for (int i = tid; i < BROWS * H; i += NTHR) { h1[i] = 0.0f; h2[i] = 0.0f; }
    for (int i = tid; i < G; i += NTHR) b2s[i] = b2[i];
    __syncthreads();

    float c1 = 0.0f, c2 = 0.0f;          // cell state owned by thread (tid<400)
    const int ur = tid / H;              // update row
    const int uu = tid % H;              // update unit

    for (int t = 0; t < T; t++) {
        // ---- layer 1: z = zx[t] + h1_prev @ k1h ----
        if (tid < G) {
            const int c = tid;
            const float* zxp = zx + ((long long)b0 * T + t) * G + c;
            float a0 = zxp[0 * T * G];
            float a1 = zxp[1 * T * G];
            float a2 = zxp[2 * T * G];
            float a3 = zxp[3 * T * G];
            const float4* hv = (const float4*)h1;
            #pragma unroll 5
            for (int kk = 0; kk < H / 4; kk++) {
                float4 v0 = hv[0 * (H / 4) + kk];
                float4 v1 = hv[1 * (H / 4) + kk];
                float4 v2 = hv[2 * (H / 4) + kk];
                float4 v3 = hv[3 * (H / 4) + kk];
                float w0 = k1h[(kk * 4 + 0) * G + c];
                float w1 = k1h[(kk * 4 + 1) * G + c];
                float w2 = k1h[(kk * 4 + 2) * G + c];
                float w3 = k1h[(kk * 4 + 3) * G + c];
                a0 += v0.x * w0 + v0.y * w1 + v0.z * w2 + v0.w * w3;
                a1 += v1.x * w0 + v1.y * w1 + v1.z * w2 + v1.w * w3;
                a2 += v2.x * w0 + v2.y * w1 + v2.z * w2 + v2.w * w3;
                a3 += v3.x * w0 + v3.y * w1 + v3.z * w2 + v3.w * w3;
            }
            zs[0 * G + c] = a0;
            zs[1 * G + c] = a1;
            zs[2 * G + c] = a2;
            zs[3 * G + c] = a3;
        }
        __syncthreads();

        // ---- layer 1 gates ----
        if (tid < BROWS * H) {
            float zi = zs[ur * G + uu];
            float zj = zs[ur * G + uu + H];
            float zf = zs[ur * G + uu + 2 * H];
            float zo = zs[ur * G + uu + 3 * H];
            c1 = c1 * sigm(zf + 1.0f) + sigm(zi) * mytanh(zj);
            h1[ur * H + uu] = mytanh(c1) * sigm(zo);
        }
        __syncthreads();

        // ---- layer 2: z = [h1_new, h2_prev] @ k2 + b2 ----
        if (tid < G) {
            const int c = tid;
            float a0 = b2s[c], a1 = a0, a2 = a0, a3 = a0;
            const float4* h1v = (const float4*)h1;
            const float4* h2v = (const float4*)h2;
            #pragma unroll 5
            for (int kk = 0; kk < H / 4; kk++) {
                float4 v0 = h1v[0 * (H / 4) + kk];
                float4 v1 = h1v[1 * (H / 4) + kk];
                float4 v2 = h1v[2 * (H / 4) + kk];
                float4 v3 = h1v[3 * (H / 4) + kk];
                float w0 = __ldg(&k2[(kk * 4 + 0) * G + c]);
                float w1 = __ldg(&k2[(kk * 4 + 1) * G + c]);
                float w2 = __ldg(&k2[(kk * 4 + 2) * G + c]);
                float w3 = __ldg(&k2[(kk * 4 + 3) * G + c]);
                a0 += v0.x * w0 + v0.y * w1 + v0.z * w2 + v0.w * w3;
                a1 += v1.x * w0 + v1.y * w1 + v1.z * w2 + v1.w * w3;
                a2 += v2.x * w0 + v2.y * w1 + v2.z * w2 + v2.w * w3;
                a3 += v3.x * w0 + v3.y * w1 + v3.z * w2 + v3.w * w3;
            }
            #pragma unroll 5
            for (int kk = 0; kk < H / 4; kk++) {
                float4 v0 = h2v[0 * (H / 4) + kk];
                float4 v1 = h2v[1 * (H / 4) + kk];
                float4 v2 = h2v[2 * (H / 4) + kk];
                float4 v3 = h2v[3 * (H / 4) + kk];
                float w0 = __ldg(&k2[(H + kk * 4 + 0) * G + c]);
                float w1 = __ldg(&k2[(H + kk * 4 + 1) * G + c]);
                float w2 = __ldg(&k2[(H + kk * 4 + 2) * G + c]);
                float w3 = __ldg(&k2[(H + kk * 4 + 3) * G + c]);
                a0 += v0.x * w0 + v0.y * w1 + v0.z * w2 + v0.w * w3;
                a1 += v1.x * w0 + v1.y * w1 + v1.z * w2 + v1.w * w3;
                a2 += v2.x * w0 + v2.y * w1 + v2.z * w2 + v2.w * w3;
                a3 += v3.x * w0 + v3.y * w1 + v3.z * w2 + v3.w * w3;
            }
            zs[0 * G + c] = a0;
            zs[1 * G + c] = a1;
            zs[2 * G + c] = a2;
            zs[3 * G + c] = a3;
        }
        __syncthreads();

        // ---- layer 2 gates ----
        if (tid < BROWS * H) {
            float zi = zs[ur * G + uu];
            float zj = zs[ur * G + uu + H];
            float zf = zs[ur * G + uu + 2 * H];
            float zo = zs[ur * G + uu + 3 * H];
            c2 = c2 * sigm(zf + 1.0f) + sigm(zi) * mytanh(zj);
            h2[ur * H + uu] = mytanh(c2) * sigm(zo);
        }
        __syncthreads();
    }

    // ---- FC head: fc1 = h2 @ wfc1 + bfc1 ; pred = fc1 @ wfc2 + bfc2 ----
    if (tid < BROWS * FCW) {
        int r = tid / FCW, j = tid % FCW;
        float a = bfc1[j];
        #pragma unroll 4
        for (int k = 0; k < H; k++)
            a += h2[r * H + k] * wfc1[k * FCW + j];
        zs[r * FCW + j] = a;   // reuse zs as fc1 buffer
    }
    __syncthreads();
    if (tid < BROWS * NC) {
        int r = tid / NC, cc = tid % NC;
        float a = bfc2[cc];
        #pragma unroll 8
        for (int k = 0; k < FCW; k++)
            a += zs[r * FCW + k] * wfc2[k * NC + cc];
        out[(b0 + r) * NC + cc] = a;
    }
}

// ---------------------------------------------------------------------------
extern "C" void kernel_launch(void* const* d_in, const int* in_sizes, int n_in,
                              void* d_out, int out_size)
{
    const int*   feats = (const int*)  d_in[0];  // [512,25] int32
    const float* emb   = (const float*)d_in[1];  // [400001,100]
    const float* k1    = (const float*)d_in[2];  // [200,400]
    const float* b1    = (const float*)d_in[3];  // [400]
    const float* k2    = (const float*)d_in[4];  // [200,400]
    const float* b2    = (const float*)d_in[5];  // [400]
    const float* wfc1  = (const float*)d_in[6];  // [100,128]
    const float* bfc1  = (const float*)d_in[7];  // [128]
    const float* wfc2  = (const float*)d_in[8];  // [128,2]
    const float* bfc2  = (const float*)d_in[9];  // [2]
    float* out = (float*)d_out;                  // [512,2]

    float* zx = nullptr;
    cudaGetSymbolAddress((void**)&zx, g_zx);

    cudaFuncSetAttribute(lstm_seq_kernel,
                         cudaFuncAttributeMaxDynamicSharedMemorySize,
                         SM_FLOATS * (int)sizeof(float));

    embed_zx_kernel<<<BATCH, NTHR>>>(feats, emb, k1, b1, zx);
    lstm_seq_kernel<<<NBLK, NTHR, SM_FLOATS * sizeof(float)>>>(
        zx, k1, k2, b2, wfc1, bfc1, wfc2, bfc2, out);
}

// round 3
// speedup vs baseline: 1.2495x; 1.2478x over previous
#include <cuda_runtime.h>

#define T25   25
#define HID   100
#define G4    400
#define NROWS 12800           // 512*25

typedef unsigned long long u64;

__device__ float g_zx1[(size_t)NROWS * G4];   // layer1 input projection (incl b1)
__device__ float g_z2x[(size_t)NROWS * G4];   // layer2 input projection (incl b2)
__device__ float g_h1 [(size_t)NROWS * HID];  // layer1 hidden states, all t

union U4 { float4 f4; ulonglong2 u2; };
union U2 { float2 f2; u64 u; };

__device__ __forceinline__ u64 pk(float lo, float hi) {
    u64 r; asm("mov.b64 %0, {%1,%2};" : "=l"(r) : "f"(lo), "f"(hi)); return r;
}
__device__ __forceinline__ void ffma2(u64& d, u64 a, u64 b) {
    asm("fma.rn.f32x2 %0, %1, %2, %0;" : "+l"(d) : "l"(a), "l"(b));
}
__device__ __forceinline__ float hsum(u64 v) {
    float a, b; asm("mov.b64 {%0,%1}, %2;" : "=f"(a), "=f"(b) : "l"(v)); return a + b;
}
__device__ __forceinline__ float sigm(float x)   { return 1.0f / (1.0f + __expf(-x)); }
__device__ __forceinline__ float mytanh(float x) { float e = __expf(-2.0f * x); return (1.0f - e) / (1.0f + e); }

// ---------------------------------------------------------------------------
// Input-projection GEMM: out[row][c] = bias[c] + sum_k src(row)[k] * W[k][c]
// 12800 rows; block = 100 rows x 400 cols; 128 blocks, 800 threads.
// x staged TRANSPOSED in smem [k][row] so row-pair FFMA2 works; thread = col c,
// handles 52 (rg=0) or 48 (rg=1) rows as 26/24 packed accumulators.
// ---------------------------------------------------------------------------
template<int NQ>
__device__ __forceinline__ void inproj_main(
    const float (*xs)[104], const float* __restrict__ W,
    int c, int rb, float bv, float* __restrict__ out, int row0)
{
    u64 acc[2 * NQ];
    u64 binit = pk(bv, bv);
    #pragma unroll
    for (int p = 0; p < 2 * NQ; p++) acc[p] = binit;

    #pragma unroll 2
    for (int k = 0; k < HID; k++) {
        float w = __ldg(W + k * G4 + c);
        u64 wd = pk(w, w);
        const float* xr = &xs[k][rb];
        #pragma unroll
        for (int q = 0; q < NQ; q++) {
            U4 x; x.f4 = *(const float4*)(xr + 4 * q);
            ffma2(acc[2 * q],     x.u2.x, wd);
            ffma2(acc[2 * q + 1], x.u2.y, wd);
        }
    }
    #pragma unroll
    for (int p = 0; p < 2 * NQ; p++) {
        U2 v; v.u = acc[p];
        out[(long long)(row0 + rb + 2 * p) * G4 + c]     = v.f2.x;
        out[(long long)(row0 + rb + 2 * p + 1) * G4 + c] = v.f2.y;
    }
}

__global__ void __launch_bounds__(800, 1) inproj_kernel(
    const float* __restrict__ src,    // [12800][100] or null (then gather emb)
    const int*   __restrict__ feats,  // [12800] or null
    const float* __restrict__ emb,    // [VOCAB][100]
    const float* __restrict__ W,      // [100][400]
    const float* __restrict__ bias,   // [400]
    float*       __restrict__ out)    // [12800][400]
{
    __shared__ __align__(16) float xs[HID][104];   // transposed [k][row]
    const int tid  = threadIdx.x;
    const int row0 = blockIdx.x * 100;

    // stage x transposed: idx = j4*25 + rl  (lanes sweep rl -> conflict-free STS)
    for (int idx = tid; idx < 25 * 100; idx += 800) {
        int j4 = idx / 100, rl = idx % 100;
        const float* base = feats
            ? emb + (long long)__ldg(feats + row0 + rl) * HID
            : src + (long long)(row0 + rl) * HID;
        float4 v = *(const float4*)(base + 4 * j4);
        xs[4 * j4 + 0][rl] = v.x;
        xs[4 * j4 + 1][rl] = v.y;
        xs[4 * j4 + 2][rl] = v.z;
        xs[4 * j4 + 3][rl] = v.w;
    }
    __syncthreads();

    const int c  = tid % G4;
    const int rg = tid / G4;          // 0: rows 0..51, 1: rows 52..99
    const float bv = bias[c];
    if (rg == 0) inproj_main<13>(xs, W, c, 0,  bv, out, row0);
    else         inproj_main<12>(xs, W, c, 52, bv, out, row0);
}

// ---------------------------------------------------------------------------
// Recurrence kernel (one LSTM layer). zin = precomputed x-projection (incl
// bias). Recurrent weights (h-half, [100][400]) live in registers, k split
// across two 400-thread groups; partials reduced via smem.
// Block = 4 batch rows, grid 128, 800 threads.
// ---------------------------------------------------------------------------
__global__ void __launch_bounds__(800, 1) rec_kernel(
    const float* __restrict__ zin,    // [12800][400]
    const float* __restrict__ Wh,     // [100][400]
    float*       __restrict__ h_out,  // [12800][100] or null
    const float* __restrict__ wfc1, const float* __restrict__ bfc1,
    const float* __restrict__ wfc2, const float* __restrict__ bfc2,
    float*       __restrict__ out)    // [512][2] or null
{
    __shared__ __align__(16) float hs[4][104];      // h state, zero-padded k
    __shared__ float zp[2][4][G4];                  // k-split partials
    __shared__ float fc1s[4][128];

    const int tid = threadIdx.x;
    const int b0  = blockIdx.x * 4;
    const int c   = tid % G4;
    const int kh  = tid / G4;                        // k half: 0 or 1

    // preload my 52 weights (k in [kh*52, kh*52+52), zeros beyond k=99)
    u64 wp[26];
    #pragma unroll
    for (int j = 0; j < 26; j++) {
        int k = kh * 52 + 2 * j;
        float w0 = (k     < HID) ? __ldg(Wh + (k    ) * G4 + c) : 0.f;
        float w1 = (k + 1 < HID) ? __ldg(Wh + (k + 1) * G4 + c) : 0.f;
        wp[j] = pk(w0, w1);
    }
    for (int i = tid; i < 4 * 104; i += 800) ((float*)hs)[i] = 0.f;
    __syncthreads();

    const int gr = tid / 100;    // valid when tid < 400
    const int gu = tid % 100;
    float cst = 0.f;

    for (int t = 0; t < T25; t++) {
        // prefetch this step's x-projection for the gate phase
        float zx0 = 0.f, zx1 = 0.f, zx2 = 0.f, zx3 = 0.f;
        if (tid < 400) {
            const float* zr = zin + ((long long)(b0 + gr) * T25 + t) * G4;
            zx0 = __ldg(zr + gu);
            zx1 = __ldg(zr + gu + 100);
            zx2 = __ldg(zr + gu + 200);
            zx3 = __ldg(zr + gu + 300);
        }

        // partial GEMM over my k half: acc[r] = sum_k h[r][k] * w[k][c]
        u64 acc[4] = {0ULL, 0ULL, 0ULL, 0ULL};
        const int kb = kh * 52;
        #pragma unroll
        for (int j4 = 0; j4 < 13; j4++) {
            #pragma unroll
            for (int r = 0; r < 4; r++) {
                U4 hv; hv.f4 = *(const float4*)&hs[r][kb + 4 * j4];
                ffma2(acc[r], hv.u2.x, wp[2 * j4]);
                ffma2(acc[r], hv.u2.y, wp[2 * j4 + 1]);
            }
        }
        zp[kh][0][c] = hsum(acc[0]);
        zp[kh][1][c] = hsum(acc[1]);
        zp[kh][2][c] = hsum(acc[2]);
        zp[kh][3][c] = hsum(acc[3]);
        __syncthreads();

        if (tid < 400) {
            float zi = zx0 + zp[0][gr][gu]       + zp[1][gr][gu];
            float zj = zx1 + zp[0][gr][gu + 100] + zp[1][gr][gu + 100];
            float zf = zx2 + zp[0][gr][gu + 200] + zp[1][gr][gu + 200];
            float zo = zx3 + zp[0][gr][gu + 300] + zp[1][gr][gu + 300];
            cst = cst * sigm(zf + 1.0f) + sigm(zi) * mytanh(zj);
            float hn = mytanh(cst) * sigm(zo);
            hs[gr][gu] = hn;
            if (h_out) h_out[((long long)(b0 + gr) * T25 + t) * HID + gu] = hn;
        }
        __syncthreads();
    }

    if (out) {
        if (tid < 512) {
            int r = tid / 128, j = tid % 128;
            float a = bfc1[j];
            #pragma unroll 4
            for (int k = 0; k < HID; k++)
                a += hs[r][k] * __ldg(wfc1 + k * 128 + j);
            fc1s[r][j] = a;
        }
        __syncthreads();
        if (tid < 8) {
            int r = tid / 2, cc = tid % 2;
            float a = bfc2[cc];
            #pragma unroll 8
            for (int k = 0; k < 128; k++)
                a += fc1s[r][k] * __ldg(wfc2 + k * 2 + cc);
            out[(b0 + r) * 2 + cc] = a;
        }
    }
}

// ---------------------------------------------------------------------------
extern "C" void kernel_launch(void* const* d_in, const int* in_sizes, int n_in,
                              void* d_out, int out_size)
{
    const int*   feats = (const int*)  d_in[0];  // [512,25]
    const float* emb   = (const float*)d_in[1];  // [400001,100]
    const float* k1    = (const float*)d_in[2];  // [200,400]
    const float* b1    = (const float*)d_in[3];  // [400]
    const float* k2    = (const float*)d_in[4];  // [200,400]
    const float* b2    = (const float*)d_in[5];  // [400]
    const float* wfc1  = (const float*)d_in[6];  // [100,128]
    const float* bfc1  = (const float*)d_in[7];  // [128]
    const float* wfc2  = (const float*)d_in[8];  // [128,2]
    const float* bfc2  = (const float*)d_in[9];  // [2]
    float* out = (float*)d_out;                  // [512,2]

    float *zx1, *z2x, *h1;
    cudaGetSymbolAddress((void**)&zx1, g_zx1);
    cudaGetSymbolAddress((void**)&z2x, g_z2x);
    cudaGetSymbolAddress((void**)&h1,  g_h1);

    // A: zx1 = emb[feats] @ k1[0:100] + b1
    inproj_kernel<<<128, 800>>>(nullptr, feats, emb, k1, b1, zx1);
    // B: layer-1 recurrence -> h1 (all timesteps)
    rec_kernel<<<128, 800>>>(zx1, k1 + HID * G4, h1,
                             nullptr, nullptr, nullptr, nullptr, nullptr);
    // C: z2x = h1 @ k2[0:100] + b2
    inproj_kernel<<<128, 800>>>(h1, nullptr, nullptr, k2, b2, z2x);
    // D: layer-2 recurrence + FC head -> out
    rec_kernel<<<128, 800>>>(z2x, k2 + HID * G4, nullptr,
                             wfc1, bfc1, wfc2, bfc2, out);
}